// round 5
// baseline (speedup 1.0000x reference)
#include <cuda_runtime.h>
#include <math_constants.h>
#include <cstdint>

// Problem constants (fixed by the dataset)
#define Nn   20000
#define Ee   100000
#define INDIM 256
#define Dd   512
#define Hh   4
#define HD   2048        // Hh * Dd
#define SLOPE 0.2f

typedef unsigned long long ull;

// ---------------------------------------------------------------------------
// Scratch (device globals: allocation-free per harness rules)
// ---------------------------------------------------------------------------
__device__ float g_feat_src[(size_t)Nn * HD];   // 164 MB
__device__ float g_feat_dst[(size_t)Nn * HD];   // 164 MB
__device__ float g_rst[(size_t)Nn * HD];        // 164 MB
__device__ float g_score[Ee * Hh];
__device__ float g_max[Nn * Hh];
__device__ float g_denom[Nn * Hh];
__device__ float g_effbias[Dd];

// ---------------------------------------------------------------------------
// Helpers
// ---------------------------------------------------------------------------
__device__ __forceinline__ float lrelu(float x) {
    return x > 0.0f ? x : SLOPE * x;
}

// Packed dual-fp32 FMA (Blackwell f32x2 pipe — 2x scalar FFMA throughput)
#define FMA2(d, a, b) \
    asm("fma.rn.f32x2 %0, %1, %2, %0;" : "+l"(d) : "l"(a), "l"(b))
#define PACK2(d, lo, hi) \
    asm("mov.b64 %0, {%1, %2};" : "=l"(d) : "f"(lo), "f"(hi))
#define UNPACK2(lo, hi, v) \
    asm("mov.b64 {%0, %1}, %2;" : "=f"(lo), "=f"(hi) : "l"(v))

__device__ __forceinline__ void redAddF4(float4* p, float4 v) {
    asm volatile("red.global.add.v4.f32 [%0], {%1, %2, %3, %4};"
                 :: "l"(__cvta_generic_to_global(p)),
                    "f"(v.x), "f"(v.y), "f"(v.z), "f"(v.w)
                 : "memory");
}

__device__ __forceinline__ void atomicMaxFloat(float* addr, float val) {
    int old = __float_as_int(*addr);
    while (__int_as_float(old) < val) {
        int assumed = old;
        old = atomicCAS((int*)addr, assumed, __float_as_int(val));
        if (old == assumed) break;
    }
}

// ---------------------------------------------------------------------------
// Init: rst = 0, max = -inf, denom = 0, effbias = b_fc
// ---------------------------------------------------------------------------
__global__ void k_init(const float* __restrict__ b_fc) {
    size_t idx = (size_t)blockIdx.x * blockDim.x + threadIdx.x;
    float4* r4 = (float4*)g_rst;
    size_t tot4 = (size_t)Nn * HD / 4;
    size_t stride = (size_t)gridDim.x * blockDim.x;
    for (size_t i = idx; i < tot4; i += stride)
        r4[i] = make_float4(0.f, 0.f, 0.f, 0.f);
    if (idx < (size_t)Nn * Hh) {
        g_max[idx] = -CUDART_INF_F;
        g_denom[idx] = 0.f;
    }
    if (idx < Dd)
        g_effbias[idx] = b_fc[idx];
}

// ---------------------------------------------------------------------------
// Effective fc bias partials: eff[j] += sum_{k in chunk} gat_bias[k]*W_fc[k,j]
// 16 blocks x 512 threads; coalesced W_fc reads; atomic accumulation.
// ---------------------------------------------------------------------------
__global__ __launch_bounds__(512)
void k_fcbias(const float* __restrict__ gat_bias,
              const float* __restrict__ W_fc) {
    int j = threadIdx.x;                 // 0..511 == Dd
    int k0 = blockIdx.x * (HD / 16);     // 16 chunks of 128
    float acc = 0.f;
    #pragma unroll 8
    for (int k = k0; k < k0 + HD / 16; ++k)
        acc = fmaf(gat_bias[k], W_fc[(size_t)k * Dd + j], acc);
    atomicAdd(&g_effbias[j], acc);
}

// ---------------------------------------------------------------------------
// SGEMM: C[M, Ncols] = A[M, K] @ B[K, Ncols] + bias[Ncols], optional LeakyReLU
// 128x128x16 tiling, 256 threads, 8x8 per thread, double-buffered smem,
// inner product on packed f32x2 FMA (dual fp32 pipe).
// K multiple of 16, Ncols multiple of 128 (holds: 256/2048/512).
// ---------------------------------------------------------------------------
#define TM 128
#define TN 128
#define TK 16

__global__ __launch_bounds__(256)
void sgemm_bias(const float* __restrict__ A, const float* __restrict__ B,
                const float* __restrict__ bias, float* __restrict__ C,
                int M, int Ncols, int K, int do_lrelu) {
    __shared__ float As[2][TK][TM];
    __shared__ float Bs[2][TK][TN];

    const int tid = threadIdx.x;
    const int rowBase = blockIdx.y * TM;
    const int colBase = blockIdx.x * TN;

    // A loader: float4 along K; covers 64 rows/pass, 2 passes
    const int aRow = tid >> 2;          // 0..63
    const int aCol = (tid & 3) << 2;    // 0,4,8,12
    // B loader: float4 along N; 8 k-rows/pass, 2 passes
    const int bRow = tid >> 5;          // 0..7
    const int bCol = (tid & 31) << 2;   // 0..124

    const int tRow = (tid >> 4) << 3;   // 0..120 step 8
    const int tCol = (tid & 15) << 3;   // 0..120 step 8

    ull acc[8][4];                      // [mi][n-pair], packed f32x2
    #pragma unroll
    for (int i = 0; i < 8; ++i)
        #pragma unroll
        for (int j = 0; j < 4; ++j) acc[i][j] = 0ULL;

    float4 aReg[2], bReg[2];

    // ---- prologue: load tile 0 ----
    {
        #pragma unroll
        for (int p = 0; p < 2; ++p) {
            int gRow = rowBase + aRow + p * 64;
            aReg[p] = make_float4(0.f, 0.f, 0.f, 0.f);
            if (gRow < M)
                aReg[p] = *(const float4*)(A + (size_t)gRow * K + aCol);
            bReg[p] = *(const float4*)(B + (size_t)(bRow + p * 8) * Ncols + colBase + bCol);
        }
        #pragma unroll
        for (int p = 0; p < 2; ++p) {
            int r = aRow + p * 64;
            As[0][aCol + 0][r] = aReg[p].x;
            As[0][aCol + 1][r] = aReg[p].y;
            As[0][aCol + 2][r] = aReg[p].z;
            As[0][aCol + 3][r] = aReg[p].w;
            *(float4*)(&Bs[0][bRow + p * 8][bCol]) = bReg[p];
        }
    }
    __syncthreads();

    const int T = K / TK;
    int cur = 0;
    for (int t = 0; t < T; ++t) {
        int k0n = (t + 1) * TK;
        // prefetch next tile into registers
        if (t + 1 < T) {
            #pragma unroll
            for (int p = 0; p < 2; ++p) {
                int gRow = rowBase + aRow + p * 64;
                aReg[p] = make_float4(0.f, 0.f, 0.f, 0.f);
                if (gRow < M)
                    aReg[p] = *(const float4*)(A + (size_t)gRow * K + k0n + aCol);
                bReg[p] = *(const float4*)(B + (size_t)(k0n + bRow + p * 8) * Ncols + colBase + bCol);
            }
        }

        // compute current tile (packed f32x2 FMAs)
        #pragma unroll
        for (int kk = 0; kk < TK; ++kk) {
            float regM[8];
            #pragma unroll
            for (int i = 0; i < 8; i += 4)
                *(float4*)(&regM[i]) = *(const float4*)(&As[cur][kk][tRow + i]);
            ull regN[4];
            {
                const ulonglong2* bp = (const ulonglong2*)(&Bs[cur][kk][tCol]);
                ulonglong2 n0 = bp[0], n1 = bp[1];
                regN[0] = n0.x; regN[1] = n0.y; regN[2] = n1.x; regN[3] = n1.y;
            }
            #pragma unroll
            for (int i = 0; i < 8; ++i) {
                ull m2;
                PACK2(m2, regM[i], regM[i]);
                #pragma unroll
                for (int jp = 0; jp < 4; ++jp)
                    FMA2(acc[i][jp], m2, regN[jp]);
            }
        }

        // stage next tile into the other buffer
        if (t + 1 < T) {
            int nxt = cur ^ 1;
            #pragma unroll
            for (int p = 0; p < 2; ++p) {
                int r = aRow + p * 64;
                As[nxt][aCol + 0][r] = aReg[p].x;
                As[nxt][aCol + 1][r] = aReg[p].y;
                As[nxt][aCol + 2][r] = aReg[p].z;
                As[nxt][aCol + 3][r] = aReg[p].w;
                *(float4*)(&Bs[nxt][bRow + p * 8][bCol]) = bReg[p];
            }
            __syncthreads();
            cur = nxt;
        }
    }

    // ---- epilogue ----
    #pragma unroll
    for (int i = 0; i < 8; ++i) {
        int gRow = rowBase + tRow + i;
        if (gRow >= M) continue;
        float vout[8];
        #pragma unroll
        for (int jp = 0; jp < 4; ++jp)
            UNPACK2(vout[2 * jp], vout[2 * jp + 1], acc[i][jp]);
        #pragma unroll
        for (int j = 0; j < 8; j += 4) {
            int gCol = colBase + tCol + j;
            float4 bv = *(const float4*)(bias + gCol);
            float4 v;
            v.x = vout[j + 0] + bv.x;
            v.y = vout[j + 1] + bv.y;
            v.z = vout[j + 2] + bv.z;
            v.w = vout[j + 3] + bv.w;
            if (do_lrelu) {
                v.x = lrelu(v.x); v.y = lrelu(v.y);
                v.z = lrelu(v.z); v.w = lrelu(v.w);
            }
            *(float4*)(C + (size_t)gRow * Ncols + gCol) = v;
        }
    }
}

// ---------------------------------------------------------------------------
// Edge score: score[e,h] = sum_d lrelu(fs[src[e],h,d] + fd[dst[e],h,d]) * attn[h,d]
// plus running max per (dst, h). One warp per edge.
// ---------------------------------------------------------------------------
__global__ __launch_bounds__(256)
void k_score(const int* __restrict__ src, const int* __restrict__ dst,
             const float* __restrict__ attn) {
    int e = blockIdx.x * 8 + (threadIdx.x >> 5);
    if (e >= Ee) return;
    int lane = threadIdx.x & 31;
    int s = src[e], t = dst[e];
    const float4* fs = (const float4*)(g_feat_src + (size_t)s * HD);
    const float4* fd = (const float4*)(g_feat_dst + (size_t)t * HD);
    const float4* at = (const float4*)attn;   // attn [H,D] flat == HD layout

    #pragma unroll
    for (int h = 0; h < Hh; ++h) {
        float acc = 0.f;
        #pragma unroll
        for (int j = 0; j < (Dd / 4) / 32; ++j) {   // 4 iters
            int i = h * (Dd / 4) + j * 32 + lane;
            float4 a = fs[i], b = fd[i], w = at[i];
            acc = fmaf(lrelu(a.x + b.x), w.x, acc);
            acc = fmaf(lrelu(a.y + b.y), w.y, acc);
            acc = fmaf(lrelu(a.z + b.z), w.z, acc);
            acc = fmaf(lrelu(a.w + b.w), w.w, acc);
        }
        #pragma unroll
        for (int o = 16; o; o >>= 1)
            acc += __shfl_xor_sync(0xffffffffu, acc, o);
        if (lane == 0) {
            g_score[e * Hh + h] = acc;
            atomicMaxFloat(&g_max[t * Hh + h], acc);
        }
    }
}

// ---------------------------------------------------------------------------
// Exp + denom: score <- exp(score - max[dst]); denom[dst] += score
// ---------------------------------------------------------------------------
__global__ void k_expsum(const int* __restrict__ dst) {
    int idx = blockIdx.x * blockDim.x + threadIdx.x;
    if (idx >= Ee * Hh) return;
    int e = idx >> 2;             // Hh == 4
    int h = idx & 3;
    int t = dst[e];
    float ex = expf(g_score[idx] - g_max[t * Hh + h]);
    g_score[idx] = ex;
    atomicAdd(&g_denom[t * Hh + h], ex);
}

// ---------------------------------------------------------------------------
// Aggregate: rst[dst] += (score/denom[dst]) * feat_src[src]  (vector RED)
// One warp per edge.
// ---------------------------------------------------------------------------
__global__ __launch_bounds__(256)
void k_agg(const int* __restrict__ src, const int* __restrict__ dst) {
    int e = blockIdx.x * 8 + (threadIdx.x >> 5);
    if (e >= Ee) return;
    int lane = threadIdx.x & 31;
    int s = src[e], t = dst[e];
    const float4* fs = (const float4*)(g_feat_src + (size_t)s * HD);
    float4* rp = (float4*)(g_rst + (size_t)t * HD);

    #pragma unroll
    for (int h = 0; h < Hh; ++h) {
        float alpha = g_score[e * Hh + h] / g_denom[t * Hh + h];
        #pragma unroll
        for (int j = 0; j < (Dd / 4) / 32; ++j) {
            int i = h * (Dd / 4) + j * 32 + lane;
            float4 v = fs[i];
            v.x *= alpha; v.y *= alpha; v.z *= alpha; v.w *= alpha;
            redAddF4(rp + i, v);
        }
    }
}

// ---------------------------------------------------------------------------
// Launch
// ---------------------------------------------------------------------------
extern "C" void kernel_launch(void* const* d_in, const int* in_sizes, int n_in,
                              void* d_out, int out_size) {
    const float* z        = (const float*)d_in[0];
    const int*   src      = (const int*)  d_in[1];
    const int*   dst      = (const int*)  d_in[2];
    const float* W_src    = (const float*)d_in[3];
    const float* b_src    = (const float*)d_in[4];
    const float* W_dst    = (const float*)d_in[5];
    const float* b_dst    = (const float*)d_in[6];
    const float* attn     = (const float*)d_in[7];
    const float* gat_bias = (const float*)d_in[8];
    const float* W_fc     = (const float*)d_in[9];
    const float* b_fc     = (const float*)d_in[10];
    float* out = (float*)d_out;

    void* p;
    cudaGetSymbolAddress(&p, g_feat_src);  float* fs = (float*)p;
    cudaGetSymbolAddress(&p, g_feat_dst);  float* fd = (float*)p;
    cudaGetSymbolAddress(&p, g_rst);       float* rs = (float*)p;
    cudaGetSymbolAddress(&p, g_effbias);   float* eb = (float*)p;

    // 1. init scratch (also seeds effbias with b_fc)
    k_init<<<40000, 256>>>(b_fc);

    // 2. fold gat_bias into fc bias (parallel partials + atomics)
    k_fcbias<<<16, 512>>>(gat_bias, W_fc);

    // 3. feature GEMMs: [N,256] @ [256,2048] + bias
    dim3 g1(HD / TN, (Nn + TM - 1) / TM);
    sgemm_bias<<<g1, 256>>>(z, W_src, b_src, fs, Nn, HD, INDIM, 0);
    sgemm_bias<<<g1, 256>>>(z, W_dst, b_dst, fd, Nn, HD, INDIM, 0);

    // 4. edge scores + per-(dst,h) max
    k_score<<<(Ee + 7) / 8, 256>>>(src, dst, attn);

    // 5. exp + denom
    k_expsum<<<(Ee * Hh + 255) / 256, 256>>>(dst);

    // 6. weighted scatter-aggregate
    k_agg<<<(Ee + 7) / 8, 256>>>(src, dst);

    // 7. final GEMM + effective bias + LeakyReLU: [N,2048] @ [2048,512]
    dim3 g2(Dd / TN, (Nn + TM - 1) / TM);
    sgemm_bias<<<g2, 256>>>(rs, W_fc, eb, out, Nn, Dd, HD, 1);
}

// round 6
// speedup vs baseline: 2.0018x; 2.0018x over previous
#include <cuda_runtime.h>
#include <cuda_bf16.h>
#include <math_constants.h>
#include <cstdint>

// Problem constants (fixed by the dataset)
#define Nn   20000
#define Ee   100000
#define INDIM 256
#define Dd   512
#define Hh   4
#define HD   2048        // Hh * Dd
#define SLOPE 0.2f

// ---------------------------------------------------------------------------
// Scratch (device globals: allocation-free per harness rules)
// ---------------------------------------------------------------------------
__device__ float g_feat_src[(size_t)Nn * HD];   // 164 MB
__device__ float g_feat_dst[(size_t)Nn * HD];   // 164 MB
__device__ float g_rst[(size_t)Nn * HD];        // 164 MB
__device__ float g_score[Ee * Hh];
__device__ float g_max[Nn * Hh];
__device__ float g_denom[Nn * Hh];
__device__ float g_effbias[Dd];

// split-bf16 operands (A' = [hi|hi|lo] along K, B' = [hi;lo;hi])
__device__ __nv_bfloat16 g_zp [(size_t)Nn * 3 * INDIM];   // 30.7 MB
__device__ __nv_bfloat16 g_rp [(size_t)Nn * 3 * HD];      // 246 MB
__device__ __nv_bfloat16 g_wsp[(size_t)3 * INDIM * HD];   // 3.1 MB
__device__ __nv_bfloat16 g_wdp[(size_t)3 * INDIM * HD];   // 3.1 MB
__device__ __nv_bfloat16 g_wfp[(size_t)3 * HD * Dd];      // 6.3 MB

// ---------------------------------------------------------------------------
// Helpers
// ---------------------------------------------------------------------------
__device__ __forceinline__ float lrelu(float x) {
    return x > 0.0f ? x : SLOPE * x;
}

__device__ __forceinline__ void redAddF4(float4* p, float4 v) {
    asm volatile("red.global.add.v4.f32 [%0], {%1, %2, %3, %4};"
                 :: "l"(__cvta_generic_to_global(p)),
                    "f"(v.x), "f"(v.y), "f"(v.z), "f"(v.w)
                 : "memory");
}

__device__ __forceinline__ void atomicMaxFloat(float* addr, float val) {
    int old = __float_as_int(*addr);
    while (__int_as_float(old) < val) {
        int assumed = old;
        old = atomicCAS((int*)addr, assumed, __float_as_int(val));
        if (old == assumed) break;
    }
}

__device__ __forceinline__ uint32_t smem_u32(const void* p) {
    return (uint32_t)__cvta_generic_to_shared(p);
}

__device__ __forceinline__ void ldsm_x4(uint32_t* r, uint32_t addr) {
    asm volatile("ldmatrix.sync.aligned.m8n8.x4.shared.b16 {%0,%1,%2,%3}, [%4];"
                 : "=r"(r[0]), "=r"(r[1]), "=r"(r[2]), "=r"(r[3]) : "r"(addr));
}
__device__ __forceinline__ void ldsm_x4t(uint32_t* r, uint32_t addr) {
    asm volatile("ldmatrix.sync.aligned.m8n8.x4.trans.shared.b16 {%0,%1,%2,%3}, [%4];"
                 : "=r"(r[0]), "=r"(r[1]), "=r"(r[2]), "=r"(r[3]) : "r"(addr));
}
__device__ __forceinline__ void mma16816(float* c, const uint32_t* a, const uint32_t* b) {
    asm volatile("mma.sync.aligned.m16n8k16.row.col.f32.bf16.bf16.f32 "
                 "{%0,%1,%2,%3}, {%4,%5,%6,%7}, {%8,%9}, {%0,%1,%2,%3};"
                 : "+f"(c[0]), "+f"(c[1]), "+f"(c[2]), "+f"(c[3])
                 : "r"(a[0]), "r"(a[1]), "r"(a[2]), "r"(a[3]),
                   "r"(b[0]), "r"(b[1]));
}

__device__ __forceinline__ uint2 pack_bf4(float4 v, float4 w) {
    // pack bf16(v.x..v.w) selecting from v (already bf16-valued floats not needed)
    uint2 r;
    __nv_bfloat162 p0 = __nv_bfloat162(__float2bfloat16_rn(v.x), __float2bfloat16_rn(v.y));
    __nv_bfloat162 p1 = __nv_bfloat162(__float2bfloat16_rn(v.z), __float2bfloat16_rn(v.w));
    r.x = *(uint32_t*)&p0; r.y = *(uint32_t*)&p1;
    (void)w;
    return r;
}

// ---------------------------------------------------------------------------
// Init: rst = 0, max = -inf, denom = 0, effbias = b_fc
// ---------------------------------------------------------------------------
__global__ void k_init(const float* __restrict__ b_fc) {
    size_t idx = (size_t)blockIdx.x * blockDim.x + threadIdx.x;
    float4* r4 = (float4*)g_rst;
    size_t tot4 = (size_t)Nn * HD / 4;
    size_t stride = (size_t)gridDim.x * blockDim.x;
    for (size_t i = idx; i < tot4; i += stride)
        r4[i] = make_float4(0.f, 0.f, 0.f, 0.f);
    if (idx < (size_t)Nn * Hh) {
        g_max[idx] = -CUDART_INF_F;
        g_denom[idx] = 0.f;
    }
    if (idx < Dd)
        g_effbias[idx] = b_fc[idx];
}

// ---------------------------------------------------------------------------
// Effective fc bias partials: eff[j] += sum_{k in chunk} gat_bias[k]*W_fc[k,j]
// ---------------------------------------------------------------------------
__global__ __launch_bounds__(512)
void k_fcbias(const float* __restrict__ gat_bias,
              const float* __restrict__ W_fc) {
    int j = threadIdx.x;                 // 0..511 == Dd
    int k0 = blockIdx.x * (HD / 16);     // 16 chunks of 128
    float acc = 0.f;
    #pragma unroll 8
    for (int k = k0; k < k0 + HD / 16; ++k)
        acc = fmaf(gat_bias[k], W_fc[(size_t)k * Dd + j], acc);
    atomicAdd(&g_effbias[j], acc);
}

// ---------------------------------------------------------------------------
// Split-bf16 conversion.
// A [M,K] fp32 -> Y [M,3K] bf16 with row blocks [hi | hi | lo]
// ---------------------------------------------------------------------------
__global__ void k_cvtA(const float* __restrict__ X, __nv_bfloat16* __restrict__ Y,
                       int M, int K) {
    size_t idx = (size_t)blockIdx.x * blockDim.x + threadIdx.x;
    size_t tot = (size_t)M * (K / 4);
    if (idx >= tot) return;
    int m  = (int)(idx / (K / 4));
    int kq = (int)(idx % (K / 4)) * 4;
    float4 x = *(const float4*)(X + (size_t)m * K + kq);

    float hx = __bfloat162float(__float2bfloat16_rn(x.x));
    float hy = __bfloat162float(__float2bfloat16_rn(x.y));
    float hz = __bfloat162float(__float2bfloat16_rn(x.z));
    float hw = __bfloat162float(__float2bfloat16_rn(x.w));
    uint2 hi = pack_bf4(make_float4(hx, hy, hz, hw), x);
    uint2 lo = pack_bf4(make_float4(x.x - hx, x.y - hy, x.z - hz, x.w - hw), x);

    size_t base = (size_t)m * 3 * K + kq;
    *(uint2*)(Y + base)         = hi;
    *(uint2*)(Y + base + K)     = hi;
    *(uint2*)(Y + base + 2 * K) = lo;
}

// B [K,N] fp32 -> Y [3K,N] bf16 with K blocks [hi ; lo ; hi]
__global__ void k_cvtB(const float* __restrict__ X, __nv_bfloat16* __restrict__ Y,
                       int K, int N) {
    size_t idx = (size_t)blockIdx.x * blockDim.x + threadIdx.x;
    size_t tot = (size_t)K * (N / 4);
    if (idx >= tot) return;
    int k  = (int)(idx / (N / 4));
    int nq = (int)(idx % (N / 4)) * 4;
    float4 x = *(const float4*)(X + (size_t)k * N + nq);

    float hx = __bfloat162float(__float2bfloat16_rn(x.x));
    float hy = __bfloat162float(__float2bfloat16_rn(x.y));
    float hz = __bfloat162float(__float2bfloat16_rn(x.z));
    float hw = __bfloat162float(__float2bfloat16_rn(x.w));
    uint2 hi = pack_bf4(make_float4(hx, hy, hz, hw), x);
    uint2 lo = pack_bf4(make_float4(x.x - hx, x.y - hy, x.z - hz, x.w - hw), x);

    *(uint2*)(Y + (size_t)k * N + nq)             = hi;
    *(uint2*)(Y + (size_t)(K + k) * N + nq)       = lo;
    *(uint2*)(Y + (size_t)(2 * K + k) * N + nq)   = hi;
}

// ---------------------------------------------------------------------------
// bf16 tensor-core GEMM: C[M,N] = A[M,K]bf16 @ B[K,N]bf16 + bias, opt LeakyReLU
// 128x128 block tile, BK=32, 8 warps (4x2), each warp 32x64,
// mma.m16n8k16 with fp32 accumulate, ldmatrix fragment loads,
// register-prefetch double-buffered smem.
// Requires: N % 128 == 0, K % 32 == 0 (holds: N in {2048,512}, K in {768,6144})
// ---------------------------------------------------------------------------
#define BM 128
#define BN 128
#define BK 32
#define ASTR (BK + 8)     // 40 bf16  (80 B row stride, conflict-free ldmatrix)
#define BSTR (BN + 8)     // 136 bf16 (272 B row stride)

__global__ __launch_bounds__(256)
void gemm_bf16(const __nv_bfloat16* __restrict__ A,
               const __nv_bfloat16* __restrict__ B,
               const float* __restrict__ bias, float* __restrict__ C,
               int M, int N, int K, int do_lrelu) {
    __shared__ __nv_bfloat16 As[2][BM * ASTR];
    __shared__ __nv_bfloat16 Bs[2][BK * BSTR];

    const int tid  = threadIdx.x;
    const int lane = tid & 31;
    const int warp = tid >> 5;
    const int mw = (warp & 3) * 32;    // warp M offset within tile
    const int nw = (warp >> 2) * 64;   // warp N offset within tile

    const int rowBase = blockIdx.y * BM;
    const int colBase = blockIdx.x * BN;

    // global->smem load mapping (16B chunks)
    const int aRow = tid >> 2;            // 0..63 (+64 second pass)
    const int aCol = (tid & 3) * 8;       // 0,8,16,24
    const int bRow = tid >> 4;            // 0..15 (+16 second pass)
    const int bCol = (tid & 15) * 8;      // 0..120

    float acc[2][8][4];
    #pragma unroll
    for (int i = 0; i < 2; ++i)
        #pragma unroll
        for (int j = 0; j < 8; ++j)
            #pragma unroll
            for (int q = 0; q < 4; ++q) acc[i][j][q] = 0.f;

    uint4 aPre[2], bPre[2];

    // ldmatrix source addresses (per-lane, fixed within tile)
    const int aLdRow = lane & 15;
    const int aLdOff = (lane >> 4) * 8;
    const int bLdRow = lane & 15;
    const int bLdOff = (lane >> 4) * 8;

    // ---- prologue: fetch tile 0 ----
    #pragma unroll
    for (int p = 0; p < 2; ++p) {
        int gr = rowBase + aRow + p * 64; if (gr > M - 1) gr = M - 1;
        aPre[p] = *(const uint4*)(A + (size_t)gr * K + aCol);
        bPre[p] = *(const uint4*)(B + (size_t)(bRow + p * 16) * N + colBase + bCol);
    }
    #pragma unroll
    for (int p = 0; p < 2; ++p) {
        *(uint4*)(&As[0][(aRow + p * 64) * ASTR + aCol]) = aPre[p];
        *(uint4*)(&Bs[0][(bRow + p * 16) * BSTR + bCol]) = bPre[p];
    }
    __syncthreads();

    const int nT = K / BK;
    int cur = 0;
    for (int t = 0; t < nT; ++t) {
        // prefetch next tile into registers
        if (t + 1 < nT) {
            int k0 = (t + 1) * BK;
            #pragma unroll
            for (int p = 0; p < 2; ++p) {
                int gr = rowBase + aRow + p * 64; if (gr > M - 1) gr = M - 1;
                aPre[p] = *(const uint4*)(A + (size_t)gr * K + k0 + aCol);
                bPre[p] = *(const uint4*)(B + (size_t)(k0 + bRow + p * 16) * N + colBase + bCol);
            }
        }

        // compute current tile: 2 k16 steps
        #pragma unroll
        for (int ks = 0; ks < 2; ++ks) {
            uint32_t af[2][4];
            #pragma unroll
            for (int mt = 0; mt < 2; ++mt) {
                uint32_t addr = smem_u32(&As[cur][(mw + mt * 16 + aLdRow) * ASTR
                                                  + ks * 16 + aLdOff]);
                ldsm_x4(af[mt], addr);
            }
            uint32_t bfr[8][2];
            #pragma unroll
            for (int np = 0; np < 4; ++np) {
                uint32_t addr = smem_u32(&Bs[cur][(ks * 16 + bLdRow) * BSTR
                                                  + nw + np * 16 + bLdOff]);
                uint32_t r[4];
                ldsm_x4t(r, addr);
                bfr[np * 2][0] = r[0]; bfr[np * 2][1] = r[1];
                bfr[np * 2 + 1][0] = r[2]; bfr[np * 2 + 1][1] = r[3];
            }
            #pragma unroll
            for (int mt = 0; mt < 2; ++mt)
                #pragma unroll
                for (int nt = 0; nt < 8; ++nt)
                    mma16816(acc[mt][nt], af[mt], bfr[nt]);
        }

        // stage next tile into other buffer
        if (t + 1 < nT) {
            int nxt = cur ^ 1;
            #pragma unroll
            for (int p = 0; p < 2; ++p) {
                *(uint4*)(&As[nxt][(aRow + p * 64) * ASTR + aCol]) = aPre[p];
                *(uint4*)(&Bs[nxt][(bRow + p * 16) * BSTR + bCol]) = bPre[p];
            }
            __syncthreads();
            cur = nxt;
        }
    }

    // ---- epilogue ----
    const int g = lane >> 2;
    const int tq = lane & 3;
    #pragma unroll
    for (int mt = 0; mt < 2; ++mt) {
        #pragma unroll
        for (int nt = 0; nt < 8; ++nt) {
            int col = colBase + nw + nt * 8 + tq * 2;
            float bx = bias[col], by = bias[col + 1];
            int row0 = rowBase + mw + mt * 16 + g;
            if (row0 < M) {
                float2 v;
                v.x = acc[mt][nt][0] + bx;
                v.y = acc[mt][nt][1] + by;
                if (do_lrelu) { v.x = lrelu(v.x); v.y = lrelu(v.y); }
                *(float2*)(C + (size_t)row0 * N + col) = v;
            }
            int row1 = row0 + 8;
            if (row1 < M) {
                float2 v;
                v.x = acc[mt][nt][2] + bx;
                v.y = acc[mt][nt][3] + by;
                if (do_lrelu) { v.x = lrelu(v.x); v.y = lrelu(v.y); }
                *(float2*)(C + (size_t)row1 * N + col) = v;
            }
        }
    }
}

// ---------------------------------------------------------------------------
// Edge score: score[e,h] = sum_d lrelu(fs[src[e],h,d] + fd[dst[e],h,d]) * attn[h,d]
// plus running max per (dst, h). One warp per edge.
// ---------------------------------------------------------------------------
__global__ __launch_bounds__(256)
void k_score(const int* __restrict__ src, const int* __restrict__ dst,
             const float* __restrict__ attn) {
    int e = blockIdx.x * 8 + (threadIdx.x >> 5);
    if (e >= Ee) return;
    int lane = threadIdx.x & 31;
    int s = src[e], t = dst[e];
    const float4* fs = (const float4*)(g_feat_src + (size_t)s * HD);
    const float4* fd = (const float4*)(g_feat_dst + (size_t)t * HD);
    const float4* at = (const float4*)attn;   // attn [H,D] flat == HD layout

    #pragma unroll
    for (int h = 0; h < Hh; ++h) {
        float acc = 0.f;
        #pragma unroll
        for (int j = 0; j < (Dd / 4) / 32; ++j) {   // 4 iters
            int i = h * (Dd / 4) + j * 32 + lane;
            float4 a = fs[i], b = fd[i], w = at[i];
            acc = fmaf(lrelu(a.x + b.x), w.x, acc);
            acc = fmaf(lrelu(a.y + b.y), w.y, acc);
            acc = fmaf(lrelu(a.z + b.z), w.z, acc);
            acc = fmaf(lrelu(a.w + b.w), w.w, acc);
        }
        #pragma unroll
        for (int o = 16; o; o >>= 1)
            acc += __shfl_xor_sync(0xffffffffu, acc, o);
        if (lane == 0) {
            g_score[e * Hh + h] = acc;
            atomicMaxFloat(&g_max[t * Hh + h], acc);
        }
    }
}

// ---------------------------------------------------------------------------
// Exp + denom: score <- exp(score - max[dst]); denom[dst] += score
// ---------------------------------------------------------------------------
__global__ void k_expsum(const int* __restrict__ dst) {
    int idx = blockIdx.x * blockDim.x + threadIdx.x;
    if (idx >= Ee * Hh) return;
    int e = idx >> 2;             // Hh == 4
    int h = idx & 3;
    int t = dst[e];
    float ex = expf(g_score[idx] - g_max[t * Hh + h]);
    g_score[idx] = ex;
    atomicAdd(&g_denom[t * Hh + h], ex);
}

// ---------------------------------------------------------------------------
// Aggregate: rst[dst] += (score/denom[dst]) * feat_src[src]  (vector RED)
// ---------------------------------------------------------------------------
__global__ __launch_bounds__(256)
void k_agg(const int* __restrict__ src, const int* __restrict__ dst) {
    int e = blockIdx.x * 8 + (threadIdx.x >> 5);
    if (e >= Ee) return;
    int lane = threadIdx.x & 31;
    int s = src[e], t = dst[e];
    const float4* fs = (const float4*)(g_feat_src + (size_t)s * HD);
    float4* rp = (float4*)(g_rst + (size_t)t * HD);

    #pragma unroll
    for (int h = 0; h < Hh; ++h) {
        float alpha = g_score[e * Hh + h] / g_denom[t * Hh + h];
        #pragma unroll
        for (int j = 0; j < (Dd / 4) / 32; ++j) {
            int i = h * (Dd / 4) + j * 32 + lane;
            float4 v = fs[i];
            v.x *= alpha; v.y *= alpha; v.z *= alpha; v.w *= alpha;
            redAddF4(rp + i, v);
        }
    }
}

// ---------------------------------------------------------------------------
// Launch
// ---------------------------------------------------------------------------
extern "C" void kernel_launch(void* const* d_in, const int* in_sizes, int n_in,
                              void* d_out, int out_size) {
    const float* z        = (const float*)d_in[0];
    const int*   src      = (const int*)  d_in[1];
    const int*   dst      = (const int*)  d_in[2];
    const float* W_src    = (const float*)d_in[3];
    const float* b_src    = (const float*)d_in[4];
    const float* W_dst    = (const float*)d_in[5];
    const float* b_dst    = (const float*)d_in[6];
    const float* attn     = (const float*)d_in[7];
    const float* gat_bias = (const float*)d_in[8];
    const float* W_fc     = (const float*)d_in[9];
    const float* b_fc     = (const float*)d_in[10];
    float* out = (float*)d_out;

    void* p;
    cudaGetSymbolAddress(&p, g_feat_src); float* fs = (float*)p;
    cudaGetSymbolAddress(&p, g_feat_dst); float* fd = (float*)p;
    cudaGetSymbolAddress(&p, g_rst);      float* rs = (float*)p;
    cudaGetSymbolAddress(&p, g_effbias);  float* eb = (float*)p;
    cudaGetSymbolAddress(&p, g_zp);       __nv_bfloat16* zp  = (__nv_bfloat16*)p;
    cudaGetSymbolAddress(&p, g_rp);       __nv_bfloat16* rp  = (__nv_bfloat16*)p;
    cudaGetSymbolAddress(&p, g_wsp);      __nv_bfloat16* wsp = (__nv_bfloat16*)p;
    cudaGetSymbolAddress(&p, g_wdp);      __nv_bfloat16* wdp = (__nv_bfloat16*)p;
    cudaGetSymbolAddress(&p, g_wfp);      __nv_bfloat16* wfp = (__nv_bfloat16*)p;

    // 1. init scratch (rst=0, softmax stats, effbias=b_fc)
    k_init<<<40000, 256>>>(b_fc);

    // 2. fold gat_bias into fc bias
    k_fcbias<<<16, 512>>>(gat_bias, W_fc);

    // 3. split-bf16 conversions for the feature GEMMs
    k_cvtA<<<(Nn * (INDIM / 4) + 255) / 256, 256>>>(z, zp, Nn, INDIM);
    k_cvtB<<<(INDIM * (HD / 4) + 255) / 256, 256>>>(W_src, wsp, INDIM, HD);
    k_cvtB<<<(INDIM * (HD / 4) + 255) / 256, 256>>>(W_dst, wdp, INDIM, HD);
    k_cvtB<<<(HD * (Dd / 4) + 255) / 256, 256>>>(W_fc, wfp, HD, Dd);

    // 4. feature GEMMs (tensor cores): [N,768]bf16 @ [768,2048]bf16 + bias
    dim3 g1(HD / BN, (Nn + BM - 1) / BM);
    gemm_bf16<<<g1, 256>>>(zp, wsp, b_src, fs, Nn, HD, 3 * INDIM, 0);
    gemm_bf16<<<g1, 256>>>(zp, wdp, b_dst, fd, Nn, HD, 3 * INDIM, 0);

    // 5. edge scores + per-(dst,h) max
    k_score<<<(Ee + 7) / 8, 256>>>(src, dst, attn);

    // 6. exp + denom
    k_expsum<<<(Ee * Hh + 255) / 256, 256>>>(dst);

    // 7. weighted scatter-aggregate
    k_agg<<<(Ee + 7) / 8, 256>>>(src, dst);

    // 8. convert rst to split-bf16, then fc GEMM + effbias + LeakyReLU
    k_cvtA<<<((size_t)Nn * (HD / 4) + 255) / 256, 256>>>(rs, rp, Nn, HD);
    dim3 g2(Dd / BN, (Nn + BM - 1) / BM);
    gemm_bf16<<<g2, 256>>>(rp, wfp, eb, out, Nn, Dd, 3 * HD, 1);
}

// round 7
// speedup vs baseline: 2.5683x; 1.2830x over previous
#include <cuda_runtime.h>
#include <cuda_bf16.h>
#include <math_constants.h>
#include <cstdint>

// Problem constants (fixed by the dataset)
#define Nn   20000
#define Ee   100000
#define INDIM 256
#define Dd   512
#define Hh   4
#define HD   2048        // Hh * Dd
#define SLOPE 0.2f

// ---------------------------------------------------------------------------
// Scratch (device globals: allocation-free per harness rules)
// ---------------------------------------------------------------------------
__device__ float g_feat_src[(size_t)Nn * HD];   // 164 MB
__device__ float g_feat_dst[(size_t)Nn * HD];   // 164 MB
__device__ float g_effbias[Dd];

// CSR over dst
__device__ int g_deg[Nn];
__device__ int g_rowptr[Nn];
__device__ int g_cursor[Nn];
__device__ int g_eidx[Ee];

// split-bf16 operands (A' = [hi|hi|lo] along K, B' = [hi;lo;hi])
__device__ __nv_bfloat16 g_zp [(size_t)Nn * 3 * INDIM];   // 30.7 MB
__device__ __nv_bfloat16 g_rp [(size_t)Nn * 3 * HD];      // 246 MB
__device__ __nv_bfloat16 g_wsp[(size_t)3 * INDIM * HD];   // 3.1 MB
__device__ __nv_bfloat16 g_wdp[(size_t)3 * INDIM * HD];   // 3.1 MB
__device__ __nv_bfloat16 g_wfp[(size_t)3 * HD * Dd];      // 6.3 MB

// ---------------------------------------------------------------------------
// Helpers
// ---------------------------------------------------------------------------
__device__ __forceinline__ float lrelu(float x) {
    return x > 0.0f ? x : SLOPE * x;
}

__device__ __forceinline__ uint32_t smem_u32(const void* p) {
    return (uint32_t)__cvta_generic_to_shared(p);
}

__device__ __forceinline__ void ldsm_x4(uint32_t* r, uint32_t addr) {
    asm volatile("ldmatrix.sync.aligned.m8n8.x4.shared.b16 {%0,%1,%2,%3}, [%4];"
                 : "=r"(r[0]), "=r"(r[1]), "=r"(r[2]), "=r"(r[3]) : "r"(addr));
}
__device__ __forceinline__ void ldsm_x4t(uint32_t* r, uint32_t addr) {
    asm volatile("ldmatrix.sync.aligned.m8n8.x4.trans.shared.b16 {%0,%1,%2,%3}, [%4];"
                 : "=r"(r[0]), "=r"(r[1]), "=r"(r[2]), "=r"(r[3]) : "r"(addr));
}
__device__ __forceinline__ void mma16816(float* c, const uint32_t* a, const uint32_t* b) {
    asm volatile("mma.sync.aligned.m16n8k16.row.col.f32.bf16.bf16.f32 "
                 "{%0,%1,%2,%3}, {%4,%5,%6,%7}, {%8,%9}, {%0,%1,%2,%3};"
                 : "+f"(c[0]), "+f"(c[1]), "+f"(c[2]), "+f"(c[3])
                 : "r"(a[0]), "r"(a[1]), "r"(a[2]), "r"(a[3]),
                   "r"(b[0]), "r"(b[1]));
}

__device__ __forceinline__ uint2 pack_bf4(float a, float b, float c, float d) {
    uint2 r;
    __nv_bfloat162 p0 = __nv_bfloat162(__float2bfloat16_rn(a), __float2bfloat16_rn(b));
    __nv_bfloat162 p1 = __nv_bfloat162(__float2bfloat16_rn(c), __float2bfloat16_rn(d));
    r.x = *(uint32_t*)&p0; r.y = *(uint32_t*)&p1;
    return r;
}

// ---------------------------------------------------------------------------
// Init: effbias = b_fc, deg = cursor = 0
// ---------------------------------------------------------------------------
__global__ void k_init(const float* __restrict__ b_fc) {
    int idx = blockIdx.x * blockDim.x + threadIdx.x;
    if (idx < Dd) g_effbias[idx] = b_fc[idx];
    if (idx < Nn) { g_deg[idx] = 0; g_cursor[idx] = 0; }
}

// ---------------------------------------------------------------------------
// Effective fc bias partials: eff[j] += sum_{k in chunk} gat_bias[k]*W_fc[k,j]
// ---------------------------------------------------------------------------
__global__ __launch_bounds__(512)
void k_fcbias(const float* __restrict__ gat_bias,
              const float* __restrict__ W_fc) {
    int j = threadIdx.x;                 // 0..511 == Dd
    int k0 = blockIdx.x * (HD / 16);     // 16 chunks of 128
    float acc = 0.f;
    #pragma unroll 8
    for (int k = k0; k < k0 + HD / 16; ++k)
        acc = fmaf(gat_bias[k], W_fc[(size_t)k * Dd + j], acc);
    atomicAdd(&g_effbias[j], acc);
}

// ---------------------------------------------------------------------------
// CSR build over dst
// ---------------------------------------------------------------------------
__global__ void k_hist(const int* __restrict__ dst) {
    int e = blockIdx.x * blockDim.x + threadIdx.x;
    if (e < Ee) atomicAdd(&g_deg[dst[e]], 1);
}

__global__ __launch_bounds__(512)
void k_scan() {
    __shared__ int s[512];
    const int t = threadIdx.x;
    const int CH = (Nn + 511) / 512;   // 40
    const int base = t * CH;
    int sum = 0;
    for (int i = 0; i < CH; ++i)
        if (base + i < Nn) sum += g_deg[base + i];
    s[t] = sum;
    __syncthreads();
    for (int off = 1; off < 512; off <<= 1) {
        int v = (t >= off) ? s[t - off] : 0;
        __syncthreads();
        s[t] += v;
        __syncthreads();
    }
    int run = s[t] - sum;   // exclusive prefix of this thread's chunk
    for (int i = 0; i < CH; ++i) {
        if (base + i < Nn) {
            g_rowptr[base + i] = run;
            run += g_deg[base + i];
        }
    }
}

__global__ void k_scatter(const int* __restrict__ dst) {
    int e = blockIdx.x * blockDim.x + threadIdx.x;
    if (e >= Ee) return;
    int t = dst[e];
    int pos = g_rowptr[t] + atomicAdd(&g_cursor[t], 1);
    g_eidx[pos] = e;
}

// ---------------------------------------------------------------------------
// Split-bf16 conversion.
// A [M,K] fp32 -> Y [M,3K] bf16 with row blocks [hi | hi | lo]
// ---------------------------------------------------------------------------
__global__ void k_cvtA(const float* __restrict__ X, __nv_bfloat16* __restrict__ Y,
                       int M, int K) {
    size_t idx = (size_t)blockIdx.x * blockDim.x + threadIdx.x;
    size_t tot = (size_t)M * (K / 4);
    if (idx >= tot) return;
    int m  = (int)(idx / (K / 4));
    int kq = (int)(idx % (K / 4)) * 4;
    float4 x = *(const float4*)(X + (size_t)m * K + kq);

    float hx = __bfloat162float(__float2bfloat16_rn(x.x));
    float hy = __bfloat162float(__float2bfloat16_rn(x.y));
    float hz = __bfloat162float(__float2bfloat16_rn(x.z));
    float hw = __bfloat162float(__float2bfloat16_rn(x.w));
    uint2 hi = pack_bf4(hx, hy, hz, hw);
    uint2 lo = pack_bf4(x.x - hx, x.y - hy, x.z - hz, x.w - hw);

    size_t base = (size_t)m * 3 * K + kq;
    *(uint2*)(Y + base)         = hi;
    *(uint2*)(Y + base + K)     = hi;
    *(uint2*)(Y + base + 2 * K) = lo;
}

// B [K,N] fp32 -> Y [3K,N] bf16 with K blocks [hi ; lo ; hi]
__global__ void k_cvtB(const float* __restrict__ X, __nv_bfloat16* __restrict__ Y,
                       int K, int N) {
    size_t idx = (size_t)blockIdx.x * blockDim.x + threadIdx.x;
    size_t tot = (size_t)K * (N / 4);
    if (idx >= tot) return;
    int k  = (int)(idx / (N / 4));
    int nq = (int)(idx % (N / 4)) * 4;
    float4 x = *(const float4*)(X + (size_t)k * N + nq);

    float hx = __bfloat162float(__float2bfloat16_rn(x.x));
    float hy = __bfloat162float(__float2bfloat16_rn(x.y));
    float hz = __bfloat162float(__float2bfloat16_rn(x.z));
    float hw = __bfloat162float(__float2bfloat16_rn(x.w));
    uint2 hi = pack_bf4(hx, hy, hz, hw);
    uint2 lo = pack_bf4(x.x - hx, x.y - hy, x.z - hz, x.w - hw);

    *(uint2*)(Y + (size_t)k * N + nq)             = hi;
    *(uint2*)(Y + (size_t)(K + k) * N + nq)       = lo;
    *(uint2*)(Y + (size_t)(2 * K + k) * N + nq)   = hi;
}

// ---------------------------------------------------------------------------
// bf16 tensor-core GEMM: C[M,N] = A[M,K]bf16 @ B[K,N]bf16 + bias, opt LeakyReLU
// 128x128 block tile, BK=32, 8 warps (4x2), each warp 32x64,
// mma.m16n8k16 fp32 accumulate, ldmatrix, register-prefetch double buffer.
// ---------------------------------------------------------------------------
#define BM 128
#define BN 128
#define BK 32
#define ASTR (BK + 8)
#define BSTR (BN + 8)

__global__ __launch_bounds__(256)
void gemm_bf16(const __nv_bfloat16* __restrict__ A,
               const __nv_bfloat16* __restrict__ B,
               const float* __restrict__ bias, float* __restrict__ C,
               int M, int N, int K, int do_lrelu) {
    __shared__ __nv_bfloat16 As[2][BM * ASTR];
    __shared__ __nv_bfloat16 Bs[2][BK * BSTR];

    const int tid  = threadIdx.x;
    const int lane = tid & 31;
    const int warp = tid >> 5;
    const int mw = (warp & 3) * 32;
    const int nw = (warp >> 2) * 64;

    const int rowBase = blockIdx.y * BM;
    const int colBase = blockIdx.x * BN;

    const int aRow = tid >> 2;
    const int aCol = (tid & 3) * 8;
    const int bRow = tid >> 4;
    const int bCol = (tid & 15) * 8;

    float acc[2][8][4];
    #pragma unroll
    for (int i = 0; i < 2; ++i)
        #pragma unroll
        for (int j = 0; j < 8; ++j)
            #pragma unroll
            for (int q = 0; q < 4; ++q) acc[i][j][q] = 0.f;

    uint4 aPre[2], bPre[2];

    const int aLdRow = lane & 15;
    const int aLdOff = (lane >> 4) * 8;
    const int bLdRow = lane & 15;
    const int bLdOff = (lane >> 4) * 8;

    #pragma unroll
    for (int p = 0; p < 2; ++p) {
        int gr = rowBase + aRow + p * 64; if (gr > M - 1) gr = M - 1;
        aPre[p] = *(const uint4*)(A + (size_t)gr * K + aCol);
        bPre[p] = *(const uint4*)(B + (size_t)(bRow + p * 16) * N + colBase + bCol);
    }
    #pragma unroll
    for (int p = 0; p < 2; ++p) {
        *(uint4*)(&As[0][(aRow + p * 64) * ASTR + aCol]) = aPre[p];
        *(uint4*)(&Bs[0][(bRow + p * 16) * BSTR + bCol]) = bPre[p];
    }
    __syncthreads();

    const int nT = K / BK;
    int cur = 0;
    for (int t = 0; t < nT; ++t) {
        if (t + 1 < nT) {
            int k0 = (t + 1) * BK;
            #pragma unroll
            for (int p = 0; p < 2; ++p) {
                int gr = rowBase + aRow + p * 64; if (gr > M - 1) gr = M - 1;
                aPre[p] = *(const uint4*)(A + (size_t)gr * K + k0 + aCol);
                bPre[p] = *(const uint4*)(B + (size_t)(k0 + bRow + p * 16) * N + colBase + bCol);
            }
        }

        #pragma unroll
        for (int ks = 0; ks < 2; ++ks) {
            uint32_t af[2][4];
            #pragma unroll
            for (int mt = 0; mt < 2; ++mt) {
                uint32_t addr = smem_u32(&As[cur][(mw + mt * 16 + aLdRow) * ASTR
                                                  + ks * 16 + aLdOff]);
                ldsm_x4(af[mt], addr);
            }
            uint32_t bfr[8][2];
            #pragma unroll
            for (int np = 0; np < 4; ++np) {
                uint32_t addr = smem_u32(&Bs[cur][(ks * 16 + bLdRow) * BSTR
                                                  + nw + np * 16 + bLdOff]);
                uint32_t r[4];
                ldsm_x4t(r, addr);
                bfr[np * 2][0] = r[0]; bfr[np * 2][1] = r[1];
                bfr[np * 2 + 1][0] = r[2]; bfr[np * 2 + 1][1] = r[3];
            }
            #pragma unroll
            for (int mt = 0; mt < 2; ++mt)
                #pragma unroll
                for (int nt = 0; nt < 8; ++nt)
                    mma16816(acc[mt][nt], af[mt], bfr[nt]);
        }

        if (t + 1 < nT) {
            int nxt = cur ^ 1;
            #pragma unroll
            for (int p = 0; p < 2; ++p) {
                *(uint4*)(&As[nxt][(aRow + p * 64) * ASTR + aCol]) = aPre[p];
                *(uint4*)(&Bs[nxt][(bRow + p * 16) * BSTR + bCol]) = bPre[p];
            }
            __syncthreads();
            cur = nxt;
        }
    }

    const int g = lane >> 2;
    const int tq = lane & 3;
    #pragma unroll
    for (int mt = 0; mt < 2; ++mt) {
        #pragma unroll
        for (int nt = 0; nt < 8; ++nt) {
            int col = colBase + nw + nt * 8 + tq * 2;
            float bx = bias[col], by = bias[col + 1];
            int row0 = rowBase + mw + mt * 16 + g;
            if (row0 < M) {
                float2 v;
                v.x = acc[mt][nt][0] + bx;
                v.y = acc[mt][nt][1] + by;
                if (do_lrelu) { v.x = lrelu(v.x); v.y = lrelu(v.y); }
                *(float2*)(C + (size_t)row0 * N + col) = v;
            }
            int row1 = row0 + 8;
            if (row1 < M) {
                float2 v;
                v.x = acc[mt][nt][2] + bx;
                v.y = acc[mt][nt][3] + by;
                if (do_lrelu) { v.x = lrelu(v.x); v.y = lrelu(v.y); }
                *(float2*)(C + (size_t)row1 * N + col) = v;
            }
        }
    }
}

// ---------------------------------------------------------------------------
// Fused per-node GAT: for each (node n, head h), one warp
//   - loads fd[n] h-slice + attn h-slice into registers (once)
//   - single pass over incoming edges: score -> w=exp(score),
//     denom += w, acc += w * fs[src]   (softmax identity, no max needed:
//     scores are O(0.3), exp cannot overflow)
//   - normalizes and writes split-bf16 [hi|hi|lo] directly into g_rp
// Eliminates: g_rst (+zeroing), score/denom arrays, all edge atomics,
// the separate score/exp/aggregate passes, and the rst->bf16 conversion.
// ---------------------------------------------------------------------------
__global__ __launch_bounds__(256)
void k_node(const int* __restrict__ src, const float* __restrict__ attn) {
    int gw = blockIdx.x * 8 + (threadIdx.x >> 5);
    if (gw >= Nn * Hh) return;
    const int lane = threadIdx.x & 31;
    const int n = gw >> 2;          // 4 heads of a node in adjacent warps
    const int h = gw & 3;

    const int start = g_rowptr[n];
    const int d     = g_deg[n];

    const float4* fs4 = (const float4*)g_feat_src;
    const float4* fd4 = (const float4*)(g_feat_dst + (size_t)n * HD + h * Dd);
    const float4* at4 = (const float4*)(attn + h * Dd);

    float4 fdr[4], atr[4];
    #pragma unroll
    for (int q = 0; q < 4; ++q) {
        fdr[q] = fd4[q * 32 + lane];
        atr[q] = at4[q * 32 + lane];
    }

    float4 acc[4];
    #pragma unroll
    for (int q = 0; q < 4; ++q) acc[q] = make_float4(0.f, 0.f, 0.f, 0.f);
    float denom = 0.f;

    for (int i = 0; i < d; ++i) {
        int e = g_eidx[start + i];
        int s = src[e];
        const float4* fr = fs4 + (size_t)s * (HD / 4) + h * (Dd / 4);
        float4 a[4];
        float p = 0.f;
        #pragma unroll
        for (int q = 0; q < 4; ++q) {
            a[q] = fr[q * 32 + lane];
            p = fmaf(lrelu(a[q].x + fdr[q].x), atr[q].x, p);
            p = fmaf(lrelu(a[q].y + fdr[q].y), atr[q].y, p);
            p = fmaf(lrelu(a[q].z + fdr[q].z), atr[q].z, p);
            p = fmaf(lrelu(a[q].w + fdr[q].w), atr[q].w, p);
        }
        #pragma unroll
        for (int o = 16; o; o >>= 1)
            p += __shfl_xor_sync(0xffffffffu, p, o);
        float w = expf(p);
        denom += w;
        #pragma unroll
        for (int q = 0; q < 4; ++q) {
            acc[q].x = fmaf(w, a[q].x, acc[q].x);
            acc[q].y = fmaf(w, a[q].y, acc[q].y);
            acc[q].z = fmaf(w, a[q].z, acc[q].z);
            acc[q].w = fmaf(w, a[q].w, acc[q].w);
        }
    }

    float inv = (d > 0) ? 1.f / denom : 0.f;

    __nv_bfloat16* rp = g_rp + (size_t)n * (3 * HD);
    #pragma unroll
    for (int q = 0; q < 4; ++q) {
        float x = acc[q].x * inv, y = acc[q].y * inv,
              z = acc[q].z * inv, w = acc[q].w * inv;
        float hx = __bfloat162float(__float2bfloat16_rn(x));
        float hy = __bfloat162float(__float2bfloat16_rn(y));
        float hz = __bfloat162float(__float2bfloat16_rn(z));
        float hw = __bfloat162float(__float2bfloat16_rn(w));
        uint2 hi = pack_bf4(hx, hy, hz, hw);
        uint2 lo = pack_bf4(x - hx, y - hy, z - hz, w - hw);
        int col = h * Dd + q * 128 + lane * 4;
        *(uint2*)(rp + col)          = hi;
        *(uint2*)(rp + HD + col)     = hi;
        *(uint2*)(rp + 2 * HD + col) = lo;
    }
}

// ---------------------------------------------------------------------------
// Launch
// ---------------------------------------------------------------------------
extern "C" void kernel_launch(void* const* d_in, const int* in_sizes, int n_in,
                              void* d_out, int out_size) {
    const float* z        = (const float*)d_in[0];
    const int*   src      = (const int*)  d_in[1];
    const int*   dst      = (const int*)  d_in[2];
    const float* W_src    = (const float*)d_in[3];
    const float* b_src    = (const float*)d_in[4];
    const float* W_dst    = (const float*)d_in[5];
    const float* b_dst    = (const float*)d_in[6];
    const float* attn     = (const float*)d_in[7];
    const float* gat_bias = (const float*)d_in[8];
    const float* W_fc     = (const float*)d_in[9];
    const float* b_fc     = (const float*)d_in[10];
    float* out = (float*)d_out;

    void* p;
    cudaGetSymbolAddress(&p, g_feat_src); float* fs = (float*)p;
    cudaGetSymbolAddress(&p, g_feat_dst); float* fd = (float*)p;
    cudaGetSymbolAddress(&p, g_effbias);  float* eb = (float*)p;
    cudaGetSymbolAddress(&p, g_zp);       __nv_bfloat16* zp  = (__nv_bfloat16*)p;
    cudaGetSymbolAddress(&p, g_rp);       __nv_bfloat16* rp  = (__nv_bfloat16*)p;
    cudaGetSymbolAddress(&p, g_wsp);      __nv_bfloat16* wsp = (__nv_bfloat16*)p;
    cudaGetSymbolAddress(&p, g_wdp);      __nv_bfloat16* wdp = (__nv_bfloat16*)p;
    cudaGetSymbolAddress(&p, g_wfp);      __nv_bfloat16* wfp = (__nv_bfloat16*)p;

    // 1. init (effbias seed, CSR counters)
    k_init<<<(Nn + 511) / 512, 512>>>(b_fc);

    // 2. fold gat_bias into fc bias
    k_fcbias<<<16, 512>>>(gat_bias, W_fc);

    // 3. CSR build over dst
    k_hist<<<(Ee + 255) / 256, 256>>>(dst);
    k_scan<<<1, 512>>>();
    k_scatter<<<(Ee + 255) / 256, 256>>>(dst);

    // 4. split-bf16 conversions
    k_cvtA<<<(Nn * (INDIM / 4) + 255) / 256, 256>>>(z, zp, Nn, INDIM);
    k_cvtB<<<(INDIM * (HD / 4) + 255) / 256, 256>>>(W_src, wsp, INDIM, HD);
    k_cvtB<<<(INDIM * (HD / 4) + 255) / 256, 256>>>(W_dst, wdp, INDIM, HD);
    k_cvtB<<<(HD * (Dd / 4) + 255) / 256, 256>>>(W_fc, wfp, HD, Dd);

    // 5. feature GEMMs (tensor cores): [N,768]bf16 @ [768,2048]bf16 + bias
    dim3 g1(HD / BN, (Nn + BM - 1) / BM);
    gemm_bf16<<<g1, 256>>>(zp, wsp, b_src, fs, Nn, HD, 3 * INDIM, 0);
    gemm_bf16<<<g1, 256>>>(zp, wdp, b_dst, fd, Nn, HD, 3 * INDIM, 0);

    // 6. fused per-node attention softmax + aggregation -> split-bf16 rp
    k_node<<<(Nn * Hh + 7) / 8, 256>>>(src, attn);

    // 7. fc GEMM + effbias + LeakyReLU: [N,6144]bf16 @ [6144,512]bf16
    dim3 g2(Dd / BN, (Nn + BM - 1) / BM);
    gemm_bf16<<<g2, 256>>>(rp, wfp, eb, out, Nn, Dd, 3 * HD, 1);
}